// round 3
// baseline (speedup 1.0000x reference)
#include <cuda_runtime.h>
#include <cstddef>

// Problem constants
#define Bq   256
#define Dd   768
#define INV_SQRT_D 0.03608439182435161f   // 1/sqrt(768)

#define OUT_ELEMS  (Bq * Dd)                       // 196608
#define ATTN_ELEMS ((size_t)Bq * Dd * Dd)          // 150994944

// Scratch (no cudaMalloc allowed)
__device__ float g_q[Bq * Dd];
__device__ float g_k[Bq * Dd];
__device__ float g_v[Bq * Dd];
__device__ float g_kvs[Bq];   // (k . v) * inv_sqrt_d per row

// ---------------------------------------------------------------------------
// SGEMM (NT): C[m,n] = scale[m] * sum_k A[m,k]*W[n,k] + bias[n]
// M=256, N=768, K=768. Tiles: BM=64, BN=64, BK=16. 256 threads, 4x4 per thread.
// ---------------------------------------------------------------------------
#define BM 64
#define BN 64
#define BK 16

template<bool SCALE_A, bool BIAS>
__device__ __forceinline__
void sgemm_nt_body(const float* __restrict__ A, const float* __restrict__ W,
                   const float* __restrict__ rowscale, const float* __restrict__ bias,
                   float* __restrict__ C, int M, int N, int K)
{
    __shared__ float As[BK][BM + 4];
    __shared__ float Bs[BK][BN + 4];

    const int tid = threadIdx.x;
    const int m0 = blockIdx.y * BM;
    const int n0 = blockIdx.x * BN;

    const int lrow = tid >> 2;        // 0..63
    const int lcol = (tid & 3) * 4;   // 0,4,8,12

    const float* Aptr = A + (size_t)(m0 + lrow) * K + lcol;
    const float* Wptr = W + (size_t)(n0 + lrow) * K + lcol;

    float acc[4][4];
    #pragma unroll
    for (int i = 0; i < 4; ++i)
        #pragma unroll
        for (int j = 0; j < 4; ++j) acc[i][j] = 0.f;

    const int tx = tid & 15;   // n sub-tile
    const int ty = tid >> 4;   // m sub-tile

    for (int k0 = 0; k0 < K; k0 += BK) {
        float4 a = *(const float4*)(Aptr + k0);
        float4 w = *(const float4*)(Wptr + k0);
        As[lcol + 0][lrow] = a.x;
        As[lcol + 1][lrow] = a.y;
        As[lcol + 2][lrow] = a.z;
        As[lcol + 3][lrow] = a.w;
        Bs[lcol + 0][lrow] = w.x;
        Bs[lcol + 1][lrow] = w.y;
        Bs[lcol + 2][lrow] = w.z;
        Bs[lcol + 3][lrow] = w.w;
        __syncthreads();

        #pragma unroll
        for (int kk = 0; kk < BK; ++kk) {
            float af[4], bf[4];
            #pragma unroll
            for (int i = 0; i < 4; ++i) af[i] = As[kk][ty * 4 + i];
            #pragma unroll
            for (int j = 0; j < 4; ++j) bf[j] = Bs[kk][tx * 4 + j];
            #pragma unroll
            for (int i = 0; i < 4; ++i)
                #pragma unroll
                for (int j = 0; j < 4; ++j)
                    acc[i][j] = fmaf(af[i], bf[j], acc[i][j]);
        }
        __syncthreads();
    }

    #pragma unroll
    for (int i = 0; i < 4; ++i) {
        const int m = m0 + ty * 4 + i;
        float s = 1.f;
        if (SCALE_A) s = rowscale[m];
        #pragma unroll
        for (int j = 0; j < 4; ++j) {
            const int n = n0 + tx * 4 + j;
            float v = acc[i][j];
            if (SCALE_A) v *= s;
            if (BIAS) v += bias[n];
            C[(size_t)m * N + n] = v;
        }
    }
}

// Fused q/k/v projection: blockIdx.z selects which weight matrix / destination.
__global__ __launch_bounds__(256)
void qkv_gemm_kernel(const float* __restrict__ x,
                     const float* __restrict__ wq,
                     const float* __restrict__ wk,
                     const float* __restrict__ wv)
{
    const float* W;
    float* C;
    switch (blockIdx.z) {
        case 0:  W = wq; C = g_q; break;
        case 1:  W = wk; C = g_k; break;
        default: W = wv; C = g_v; break;
    }
    sgemm_nt_body<false, false>(x, W, nullptr, nullptr, C, Bq, Dd, Dd);
}

// Output projection with fused per-row scale (kv dot) and bias.
__global__ __launch_bounds__(256)
void out_gemm_kernel(const float* __restrict__ wo, const float* __restrict__ bo,
                     float* __restrict__ out)
{
    sgemm_nt_body<true, true>(g_q, wo, g_kvs, bo, out, Bq, Dd, Dd);
}

// ---------------------------------------------------------------------------
// kv[b] = (sum_j k[b,j]*v[b,j]) * inv_sqrt_d
// ---------------------------------------------------------------------------
__global__ __launch_bounds__(256)
void kv_dot_kernel()
{
    const int b = blockIdx.x;
    const int tid = threadIdx.x;
    float s = 0.f;
    #pragma unroll
    for (int j = tid; j < Dd; j += 256)
        s += g_k[b * Dd + j] * g_v[b * Dd + j];

    // warp reduce
    #pragma unroll
    for (int o = 16; o > 0; o >>= 1)
        s += __shfl_down_sync(0xffffffffu, s, o);

    __shared__ float red[8];
    if ((tid & 31) == 0) red[tid >> 5] = s;
    __syncthreads();
    if (tid == 0) {
        float t = 0.f;
        #pragma unroll
        for (int w = 0; w < 8; ++w) t += red[w];
        g_kvs[b] = t * INV_SQRT_D;
    }
}

// ---------------------------------------------------------------------------
// attn[b,i,j] = q[b,i] * k[b,j] * inv_sqrt_d  — streaming 604MB store kernel.
// One block = one b and 8 rows of i. 256 threads; warp writes 512B/iter.
// ---------------------------------------------------------------------------
__global__ __launch_bounds__(256)
void attn_store_kernel(float* __restrict__ attn)
{
    __shared__ float4 ks[Dd / 4];   // 192 float4 = 3KB
    __shared__ float  qs[8];

    const int b  = blockIdx.y;
    const int i0 = blockIdx.x * 8;
    const int tid = threadIdx.x;

    if (tid < Dd / 4) ks[tid] = ((const float4*)(g_k + (size_t)b * Dd))[tid];
    if (tid < 8)      qs[tid] = g_q[(size_t)b * Dd + i0 + tid] * INV_SQRT_D;
    __syncthreads();

    const int r    = tid >> 5;    // 0..7 row within tile
    const int lane = tid & 31;
    const float qi = qs[r];

    float4* out4 = (float4*)(attn + ((size_t)(b * Dd + i0 + r)) * Dd);
    #pragma unroll
    for (int u = 0; u < 6; ++u) {
        const int j4 = lane + 32 * u;
        const float4 kk = ks[j4];
        float4 o;
        o.x = qi * kk.x; o.y = qi * kk.y; o.z = qi * kk.z; o.w = qi * kk.w;
        __stcs(&out4[j4], o);   // evict-first: don't pollute L2 with 604MB
    }
}

// ---------------------------------------------------------------------------
extern "C" void kernel_launch(void* const* d_in, const int* in_sizes, int n_in,
                              void* d_out, int out_size)
{
    const float* x  = (const float*)d_in[0];
    const float* wq = (const float*)d_in[1];
    const float* wk = (const float*)d_in[2];
    const float* wv = (const float*)d_in[3];
    const float* wo = (const float*)d_in[4];
    const float* bo = (const float*)d_in[5];

    float* out  = (float*)d_out;                 // (B, D) first
    float* attn = (float*)d_out + OUT_ELEMS;     // (B, D, D) after

    const dim3 ggrid(Dd / BN, Bq / BM);          // (12, 4)
    const dim3 qkvgrid(Dd / BN, Bq / BM, 3);     // (12, 4, 3) = 144 CTAs, ~1 wave

    qkv_gemm_kernel<<<qkvgrid, 256>>>(x, wq, wk, wv);

    kv_dot_kernel<<<Bq, 256>>>();

    // out = diag(kvs) * (q @ wo.T) + bo   (kvs already includes 1/sqrt(d))
    out_gemm_kernel<<<ggrid, 256>>>(wo, bo, out);

    // attn_scores streaming store
    attn_store_kernel<<<dim3(Dd / 8, Bq), 256>>>(attn);
}

// round 6
// speedup vs baseline: 1.5420x; 1.5420x over previous
#include <cuda_runtime.h>
#include <cstddef>

// Problem constants
#define Bq   256
#define Dd   768
#define INV_SQRT_D 0.03608439182435161f   // 1/sqrt(768)

#define OUT_ELEMS  (Bq * Dd)                       // 196608

// Scratch (no cudaMalloc allowed)
__device__ float g_q[Bq * Dd];
__device__ float g_k[Bq * Dd];
__device__ float g_v[Bq * Dd];
__device__ float g_kvs[Bq];   // (k . v) * inv_sqrt_d per row

// ---------------------------------------------------------------------------
// SGEMM (NT): C[m,n] = scale[m] * sum_k A[m,k]*W[n,k] + bias[n]
// M=256, N=768, K=768. BM=BN=64, BK=16, 256 threads, 4x4/thread.
// Double-buffered smem (1 barrier per k-tile), float4 LDS + STG.
// ---------------------------------------------------------------------------
#define BM 64
#define BN 64
#define BK 16
#define NPAD 4   // row = 68 floats = 272B (16B multiple, keeps float4 alignment)

template<bool SCALE_A, bool BIAS>
__device__ __forceinline__
void sgemm_nt_body(const float* __restrict__ A, const float* __restrict__ W,
                   const float* __restrict__ rowscale, const float* __restrict__ bias,
                   float* __restrict__ C)
{
    __shared__ __align__(16) float As[2][BK][BM + NPAD];
    __shared__ __align__(16) float Bs[2][BK][BN + NPAD];

    const int tid = threadIdx.x;
    const int m0 = blockIdx.y * BM;
    const int n0 = blockIdx.x * BN;

    const int lrow  = tid >> 2;        // 0..63
    const int lcol4 = (tid & 3) * 4;   // 0,4,8,12

    const float* Aptr = A + (size_t)(m0 + lrow) * Dd + lcol4;
    const float* Wptr = W + (size_t)(n0 + lrow) * Dd + lcol4;

    const int tx = tid & 15;   // n sub-tile (x4)
    const int ty = tid >> 4;   // m sub-tile (x4)

    float acc[4][4];
    #pragma unroll
    for (int i = 0; i < 4; ++i)
        #pragma unroll
        for (int j = 0; j < 4; ++j) acc[i][j] = 0.f;

    // Prologue: tile 0 -> buffer 0
    {
        float4 a = *(const float4*)Aptr;
        float4 w = *(const float4*)Wptr;
        As[0][lcol4 + 0][lrow] = a.x;
        As[0][lcol4 + 1][lrow] = a.y;
        As[0][lcol4 + 2][lrow] = a.z;
        As[0][lcol4 + 3][lrow] = a.w;
        Bs[0][lcol4 + 0][lrow] = w.x;
        Bs[0][lcol4 + 1][lrow] = w.y;
        Bs[0][lcol4 + 2][lrow] = w.z;
        Bs[0][lcol4 + 3][lrow] = w.w;
    }
    __syncthreads();

    const int NT = Dd / BK;   // 48
    for (int t = 0; t < NT; ++t) {
        float4 an, wn;
        const bool more = (t + 1 < NT);
        if (more) {
            an = *(const float4*)(Aptr + (t + 1) * BK);
            wn = *(const float4*)(Wptr + (t + 1) * BK);
        }

        const int cb = t & 1;
        #pragma unroll
        for (int kk = 0; kk < BK; ++kk) {
            const float4 af = *(const float4*)&As[cb][kk][ty * 4];
            const float4 bf = *(const float4*)&Bs[cb][kk][tx * 4];
            acc[0][0] = fmaf(af.x, bf.x, acc[0][0]);
            acc[0][1] = fmaf(af.x, bf.y, acc[0][1]);
            acc[0][2] = fmaf(af.x, bf.z, acc[0][2]);
            acc[0][3] = fmaf(af.x, bf.w, acc[0][3]);
            acc[1][0] = fmaf(af.y, bf.x, acc[1][0]);
            acc[1][1] = fmaf(af.y, bf.y, acc[1][1]);
            acc[1][2] = fmaf(af.y, bf.z, acc[1][2]);
            acc[1][3] = fmaf(af.y, bf.w, acc[1][3]);
            acc[2][0] = fmaf(af.z, bf.x, acc[2][0]);
            acc[2][1] = fmaf(af.z, bf.y, acc[2][1]);
            acc[2][2] = fmaf(af.z, bf.z, acc[2][2]);
            acc[2][3] = fmaf(af.z, bf.w, acc[2][3]);
            acc[3][0] = fmaf(af.w, bf.x, acc[3][0]);
            acc[3][1] = fmaf(af.w, bf.y, acc[3][1]);
            acc[3][2] = fmaf(af.w, bf.z, acc[3][2]);
            acc[3][3] = fmaf(af.w, bf.w, acc[3][3]);
        }

        if (more) {
            const int nb = cb ^ 1;
            As[nb][lcol4 + 0][lrow] = an.x;
            As[nb][lcol4 + 1][lrow] = an.y;
            As[nb][lcol4 + 2][lrow] = an.z;
            As[nb][lcol4 + 3][lrow] = an.w;
            Bs[nb][lcol4 + 0][lrow] = wn.x;
            Bs[nb][lcol4 + 1][lrow] = wn.y;
            Bs[nb][lcol4 + 2][lrow] = wn.z;
            Bs[nb][lcol4 + 3][lrow] = wn.w;
            __syncthreads();
        }
    }

    #pragma unroll
    for (int i = 0; i < 4; ++i) {
        const int m = m0 + ty * 4 + i;
        float s = 1.f;
        if (SCALE_A) s = rowscale[m];
        float4 o;
        o.x = acc[i][0]; o.y = acc[i][1]; o.z = acc[i][2]; o.w = acc[i][3];
        if (SCALE_A) { o.x *= s; o.y *= s; o.z *= s; o.w *= s; }
        if (BIAS) {
            const float4 bb = *(const float4*)&bias[n0 + tx * 4];
            o.x += bb.x; o.y += bb.y; o.z += bb.z; o.w += bb.w;
        }
        *(float4*)&C[(size_t)m * Dd + n0 + tx * 4] = o;
    }
}

// Fused q/k/v projection: blockIdx.z selects weight / destination.
__global__ __launch_bounds__(256)
void qkv_gemm_kernel(const float* __restrict__ x,
                     const float* __restrict__ wq,
                     const float* __restrict__ wk,
                     const float* __restrict__ wv)
{
    const float* W;
    float* C;
    switch (blockIdx.z) {
        case 0:  W = wq; C = g_q; break;
        case 1:  W = wk; C = g_k; break;
        default: W = wv; C = g_v; break;
    }
    sgemm_nt_body<false, false>(x, W, nullptr, nullptr, C);
}

// Output projection (PDL primary): triggers attn_store launch immediately,
// then computes out = diag(kvs) * (q @ wo.T) + bo.
__global__ __launch_bounds__(256)
void out_gemm_kernel(const float* __restrict__ wo, const float* __restrict__ bo,
                     float* __restrict__ out)
{
#if __CUDA_ARCH__ >= 900
    cudaTriggerProgrammaticLaunchCompletion();
#endif
    sgemm_nt_body<true, true>(g_q, wo, g_kvs, bo, out);
}

// ---------------------------------------------------------------------------
// kv[b] = (sum_j k[b,j]*v[b,j]) * inv_sqrt_d
// ---------------------------------------------------------------------------
__global__ __launch_bounds__(256)
void kv_dot_kernel()
{
    const int b = blockIdx.x;
    const int tid = threadIdx.x;
    const float4* kk = (const float4*)(g_k + (size_t)b * Dd);
    const float4* vv = (const float4*)(g_v + (size_t)b * Dd);
    float s = 0.f;
    for (int j = tid; j < Dd / 4; j += 256) {
        const float4 a = kk[j], c = vv[j];
        s += a.x * c.x + a.y * c.y + a.z * c.z + a.w * c.w;
    }
    #pragma unroll
    for (int o = 16; o > 0; o >>= 1)
        s += __shfl_down_sync(0xffffffffu, s, o);

    __shared__ float red[8];
    if ((tid & 31) == 0) red[tid >> 5] = s;
    __syncthreads();
    if (tid == 0) {
        float t = 0.f;
        #pragma unroll
        for (int w = 0; w < 8; ++w) t += red[w];
        g_kvs[b] = t * INV_SQRT_D;
    }
}

// ---------------------------------------------------------------------------
// attn[b,i,j] = q[b,i] * k[b,j] * inv_sqrt_d — streaming 604MB store kernel.
// Launched with programmatic stream serialization: overlaps out_gemm
// (it reads only q/k, which were flushed two kernels earlier).
// ---------------------------------------------------------------------------
__global__ __launch_bounds__(256)
void attn_store_kernel(float* __restrict__ attn)
{
    __shared__ float4 ks[Dd / 4];   // 192 float4 = 3KB
    __shared__ float  qs[8];

    const int b  = blockIdx.y;
    const int i0 = blockIdx.x * 8;
    const int tid = threadIdx.x;

    if (tid < Dd / 4) ks[tid] = ((const float4*)(g_k + (size_t)b * Dd))[tid];
    if (tid < 8)      qs[tid] = g_q[(size_t)b * Dd + i0 + tid] * INV_SQRT_D;
    __syncthreads();

    const int r    = tid >> 5;    // row within tile
    const int lane = tid & 31;
    const float qi = qs[r];

    float4* out4 = (float4*)(attn + ((size_t)(b * Dd + i0 + r)) * Dd);
    #pragma unroll
    for (int u = 0; u < 6; ++u) {
        const int j4 = lane + 32 * u;
        const float4 kk = ks[j4];
        float4 o;
        o.x = qi * kk.x; o.y = qi * kk.y; o.z = qi * kk.z; o.w = qi * kk.w;
        __stcs(&out4[j4], o);   // evict-first: don't pollute L2 with 604MB
    }
}

// ---------------------------------------------------------------------------
extern "C" void kernel_launch(void* const* d_in, const int* in_sizes, int n_in,
                              void* d_out, int out_size)
{
    const float* x  = (const float*)d_in[0];
    const float* wq = (const float*)d_in[1];
    const float* wk = (const float*)d_in[2];
    const float* wv = (const float*)d_in[3];
    const float* wo = (const float*)d_in[4];
    const float* bo = (const float*)d_in[5];

    float* out  = (float*)d_out;                 // (B, D) first
    float* attn = (float*)d_out + OUT_ELEMS;     // (B, D, D) after

    const dim3 ggrid(Dd / BN, Bq / BM);          // (12, 4) = 48 CTAs
    const dim3 qkvgrid(Dd / BN, Bq / BM, 3);     // 144 CTAs ≈ 1 wave

    qkv_gemm_kernel<<<qkvgrid, 256>>>(x, wq, wk, wv);
    kv_dot_kernel<<<Bq, 256>>>();
    out_gemm_kernel<<<ggrid, 256>>>(wo, bo, out);

    // attn_store: PDL secondary — launches as soon as out_gemm's CTAs trigger,
    // overlapping the entire output GEMM with the 604MB store.
    {
        cudaLaunchConfig_t cfg = {};
        cfg.gridDim  = dim3(Dd / 8, Bq);
        cfg.blockDim = dim3(256);
        cfg.dynamicSmemBytes = 0;
        cfg.stream = 0;   // legacy default stream (same as <<<>>> above)
        cudaLaunchAttribute attrs[1];
        attrs[0].id = cudaLaunchAttributeProgrammaticStreamSerialization;
        attrs[0].val.programmaticStreamSerializationAllowed = 1;
        cfg.attrs = attrs;
        cfg.numAttrs = 1;
        cudaLaunchKernelEx(&cfg, attn_store_kernel, attn);
    }
}